// round 3
// baseline (speedup 1.0000x reference)
#include <cuda_runtime.h>
#include <cstdint>

#define NODES 207
#define HID   64
#define BATCH 64
#define BH    4096          // BATCH*HID
#define ROW   13248         // NODES*HID (per-batch state size)
#define HALF  423936u       // 32*ROW = offset between batch b and b+32 in flat index
#define KPAD  208           // 207 padded to multiple of 16
#define MPAD  256           // 207 padded to multiple of 64

// Scratch state (device globals: allocation-free rule)
__device__ float g_y[KPAD * BH];        // Y in [n][b*64+h] layout, row 207 = zeros
__device__ float g_AY[MPAD * BH];       // A @ Y
__device__ float g_Apad[MPAD * KPAD];   // zero-padded adjacency
__device__ unsigned int g_flat[256];    // per-step keys: (g_flat[2s], g_flat[2s+1])

// ---------------- JAX threefry2x32 (20 rounds) ----------------
__device__ __forceinline__ void tf2x32(unsigned k0, unsigned k1,
                                       unsigned x0, unsigned x1,
                                       unsigned &o0, unsigned &o1) {
    unsigned ks2 = k0 ^ k1 ^ 0x1BD11BDAu;
    x0 += k0; x1 += k1;
#define TFR(r) { x0 += x1; x1 = __funnelshift_l(x1, x1, (r)); x1 ^= x0; }
    TFR(13) TFR(15) TFR(26) TFR(6)
    x0 += k1;  x1 += ks2 + 1u;
    TFR(17) TFR(29) TFR(16) TFR(24)
    x0 += ks2; x1 += k0 + 2u;
    TFR(13) TFR(15) TFR(26) TFR(6)
    x0 += k0;  x1 += k1 + 3u;
    TFR(17) TFR(29) TFR(16) TFR(24)
    x0 += k1;  x1 += ks2 + 4u;
    TFR(13) TFR(15) TFR(26) TFR(6)
    x0 += ks2; x1 += k0 + 5u;
#undef TFR
    o0 = x0; o1 = x1;
}

// partitionable threefry: 32-bit word for counter i is xor of both outputs
__device__ __forceinline__ unsigned tf_bits32(unsigned k0, unsigned k1, unsigned i) {
    unsigned o0, o1;
    tf2x32(k0, k1, 0u, i, o0, o1);
    return o0 ^ o1;
}

// bits -> N(0,1) exactly as jax.random.normal (float32 path)
__device__ __forceinline__ float bits_to_normal(unsigned b) {
    float f = __uint_as_float((b >> 9) | 0x3F800000u) - 1.0f;  // [0,1)
    float u = fmaf(f, 2.0f, -0.99999994f);   // span(f32)=2.0, lo=nextafter(-1,0)
    u = fmaxf(u, -0.99999994f);
    return 1.41421356f * erfinvf(u);
}

// ---------------- init: transpose x -> g_y, pad A, compute step keys ----------------
__global__ void __launch_bounds__(512) k_init(const float* __restrict__ x,
                                              const float* __restrict__ A) {
    int gid = blockIdx.x * blockDim.x + threadIdx.x;
    int stride = gridDim.x * blockDim.x;
    for (int idx = gid; idx < KPAD * BH; idx += stride) {
        int n = idx >> 12, c = idx & 4095;
        float v = 0.0f;
        if (n < NODES) {
            int b = c >> 6, h = c & 63;
            v = x[b * ROW + n * HID + h];
        }
        g_y[idx] = v;
    }
    for (int idx = gid; idx < MPAD * KPAD; idx += stride) {
        int m = idx / KPAD, k = idx - m * KPAD;
        g_Apad[idx] = (m < NODES && k < NODES) ? A[m * NODES + k] : 0.0f;
    }
    // fold-like split (partitionable): key_s = threefry(key, 0, s), both words
    if (gid < 100) {
        unsigned o0, o1;
        tf2x32(0u, 42u, 0u, (unsigned)gid, o0, o1);
        g_flat[2 * gid]     = o0;
        g_flat[2 * gid + 1] = o1;
    }
}

// ---------------- GEMM1: g_AY[256,4096] = g_Apad[256,208] @ g_y[208,4096] ----------------
__global__ void __launch_bounds__(256) k_gemm1() {
    __shared__ float sA[16][64];    // k-major A tile
    __shared__ float sB[16][128];
    int n0 = blockIdx.x << 7;       // 32 col tiles of 128
    int m0 = blockIdx.y << 6;       // 4 row tiles of 64
    int tid = threadIdx.x;
    int tm = tid >> 4, tn = tid & 15;
    float acc[4][8];
#pragma unroll
    for (int r = 0; r < 4; r++)
#pragma unroll
        for (int c = 0; c < 8; c++) acc[r][c] = 0.0f;

    int lm = tid >> 2, lk = (tid & 3) << 2;
    for (int k0 = 0; k0 < KPAD; k0 += 16) {
        float4 a4 = *(const float4*)&g_Apad[(m0 + lm) * KPAD + k0 + lk];
        sA[lk + 0][lm] = a4.x; sA[lk + 1][lm] = a4.y;
        sA[lk + 2][lm] = a4.z; sA[lk + 3][lm] = a4.w;
#pragma unroll
        for (int i = 0; i < 2; i++) {
            int idx = tid + (i << 8);
            int kk = idx >> 5, c4 = idx & 31;
            *(float4*)&sB[kk][c4 << 2] =
                *(const float4*)&g_y[(k0 + kk) * BH + n0 + (c4 << 2)];
        }
        __syncthreads();
#pragma unroll
        for (int k = 0; k < 16; k++) {
            float4 av = *(const float4*)&sA[k][tm << 2];
            float4 b0 = *(const float4*)&sB[k][tn << 3];
            float4 b1 = *(const float4*)&sB[k][(tn << 3) + 4];
            float a[4] = {av.x, av.y, av.z, av.w};
            float bb[8] = {b0.x, b0.y, b0.z, b0.w, b1.x, b1.y, b1.z, b1.w};
#pragma unroll
            for (int r = 0; r < 4; r++)
#pragma unroll
                for (int c = 0; c < 8; c++)
                    acc[r][c] = fmaf(a[r], bb[c], acc[r][c]);
        }
        __syncthreads();
    }
#pragma unroll
    for (int r = 0; r < 4; r++) {
        float* dst = &g_AY[(m0 + (tm << 2) + r) * BH + n0 + (tn << 3)];
        *(float4*)dst       = make_float4(acc[r][0], acc[r][1], acc[r][2], acc[r][3]);
        *(float4*)(dst + 4) = make_float4(acc[r][4], acc[r][5], acc[r][6], acc[r][7]);
    }
}

// ---------------- step: two GCN heads + tanh + threefry noise + Euler-Maruyama update ----------------
// block n handles node n for all 64 batches; thread covers batches b and b+32.
__global__ void __launch_bounds__(512) k_step(int s,
        const float* __restrict__ Wt, const float* __restrict__ bt,
        const float* __restrict__ Wd, const float* __restrict__ bd) {
    __shared__ float sAY[64 * 65];          // [b][k], stride 65 (bank-conflict-free)
    int n = blockIdx.x;
    int tid = threadIdx.x;
    const float* ayrow = g_AY + n * BH;
    for (int idx = tid; idx < BH; idx += 512)
        sAY[(idx >> 6) * 65 + (idx & 63)] = ayrow[idx];
    __syncthreads();

    unsigned key0 = g_flat[2 * s], key1 = g_flat[2 * s + 1];
    int hq  = tid & 15;          // column quad (h = hq*4 + j)
    int blo = tid >> 4;          // 0..31
    float accT0[4] = {0,0,0,0}, accD0[4] = {0,0,0,0};
    float accT1[4] = {0,0,0,0}, accD1[4] = {0,0,0,0};
    const float4* Wt4 = (const float4*)Wt;
    const float4* Wd4 = (const float4*)Wd;
    const float* aL = &sAY[blo * 65];
    const float* aH = &sAY[(blo + 32) * 65];
#pragma unroll 8
    for (int k = 0; k < 64; k++) {
        float4 wt = __ldg(&Wt4[(k << 4) + hq]);
        float4 wd = __ldg(&Wd4[(k << 4) + hq]);
        float wtv[4] = {wt.x, wt.y, wt.z, wt.w};
        float wdv[4] = {wd.x, wd.y, wd.z, wd.w};
        float al = aL[k], ah = aH[k];
#pragma unroll
        for (int j = 0; j < 4; j++) {
            accT0[j] = fmaf(al, wtv[j], accT0[j]);
            accD0[j] = fmaf(al, wdv[j], accD0[j]);
            accT1[j] = fmaf(ah, wtv[j], accT1[j]);
            accD1[j] = fmaf(ah, wdv[j], accD1[j]);
        }
    }
    float4 bt4 = __ldg(&((const float4*)bt)[hq]);
    float4 bd4 = __ldg(&((const float4*)bd)[hq]);
    float btv[4] = {bt4.x, bt4.y, bt4.z, bt4.w};
    float bdv[4] = {bd4.x, bd4.y, bd4.z, bd4.w};

    // partitionable threefry noise: value index i = b*ROW + n*HID + h,
    // one eval per value, bits = out0 ^ out1 of tf(key_s, 0, i)
    float gl[4], gh[4];
    int baseidx = n * HID + (hq << 2);
#pragma unroll
    for (int j = 0; j < 4; j++) {
        unsigned ilo = (unsigned)(blo * ROW + baseidx + j);
        gl[j] = bits_to_normal(tf_bits32(key0, key1, ilo));
        gh[j] = bits_to_normal(tf_bits32(key0, key1, ilo + HALF));
    }

    float* yrow = g_y + n * BH;
    float4* pl = (float4*)&yrow[(blo << 6) + (hq << 2)];
    float4* ph = (float4*)&yrow[((blo + 32) << 6) + (hq << 2)];
    float4 vl4 = *pl, vh4 = *ph;
    float vl[4] = {vl4.x, vl4.y, vl4.z, vl4.w};
    float vh[4] = {vh4.x, vh4.y, vh4.z, vh4.w};
#pragma unroll
    for (int j = 0; j < 4; j++) {
        // y += (0.1*tanh)*dt + (0.1*tanh)*(sqrt_dt*g) ; dt=0.01, sqrt_dt=0.1
        vl[j] += 0.001f * tanhf(accT0[j] + btv[j]) + 0.01f * tanhf(accD0[j] + bdv[j]) * gl[j];
        vh[j] += 0.001f * tanhf(accT1[j] + btv[j]) + 0.01f * tanhf(accD1[j] + bdv[j]) * gh[j];
    }
    *pl = make_float4(vl[0], vl[1], vl[2], vl[3]);
    *ph = make_float4(vh[0], vh[1], vh[2], vh[3]);
}

// ---------------- output head: out[b,n,:,:] = tanh(y[b,n,:] @ W_out + b_out) ----------------
__global__ void __launch_bounds__(256) k_out(const float* __restrict__ Wo,
                                             const float* __restrict__ bo,
                                             float* __restrict__ out) {
    __shared__ float sY[BH];          // g_y row n (all 64 batches)
    __shared__ float sW[64 * 128];    // W_out[:, c0:c0+128]
    int n  = blockIdx.y;
    int c0 = blockIdx.x << 7;
    int tid = threadIdx.x;
    const float4* yr4 = (const float4*)(g_y + n * BH);
    for (int i = tid; i < 1024; i += 256) ((float4*)sY)[i] = yr4[i];
    for (int i = tid; i < 2048; i += 256) {
        int k = i >> 5, c4 = i & 31;
        ((float4*)sW)[(k << 5) + c4] = __ldg((const float4*)&Wo[k * BH + c0 + (c4 << 2)]);
    }
    __syncthreads();

    int cq = tid & 31;     // 32 col-quads -> 128 cols
    int bg = tid >> 5;     // warp id: rows b = bg + 8r
    float acc[8][4];
#pragma unroll
    for (int r = 0; r < 8; r++)
#pragma unroll
        for (int j = 0; j < 4; j++) acc[r][j] = 0.0f;
#pragma unroll 8
    for (int k = 0; k < 64; k++) {
        float4 w = *(const float4*)&sW[(k << 7) + (cq << 2)];
        float wv[4] = {w.x, w.y, w.z, w.w};
#pragma unroll
        for (int r = 0; r < 8; r++) {
            float a = sY[((bg + (r << 3)) << 6) + k];
#pragma unroll
            for (int j = 0; j < 4; j++)
                acc[r][j] = fmaf(a, wv[j], acc[r][j]);
        }
    }
    float4 bo4 = __ldg(&((const float4*)bo)[(c0 >> 2) + cq]);
    float bov[4] = {bo4.x, bo4.y, bo4.z, bo4.w};
#pragma unroll
    for (int r = 0; r < 8; r++) {
        int b = bg + (r << 3);
        float4 o;
        o.x = tanhf(acc[r][0] + bov[0]);
        o.y = tanhf(acc[r][1] + bov[1]);
        o.z = tanhf(acc[r][2] + bov[2]);
        o.w = tanhf(acc[r][3] + bov[3]);
        *(float4*)&out[(b * NODES + n) * 4096 + c0 + (cq << 2)] = o;
    }
}

// ---------------- host ----------------
extern "C" void kernel_launch(void* const* d_in, const int* in_sizes, int n_in,
                              void* d_out, int out_size) {
    const float* x  = (const float*)d_in[0];
    const float* A  = (const float*)d_in[1];
    const float* Wt = (const float*)d_in[2];
    const float* bt = (const float*)d_in[3];
    const float* Wd = (const float*)d_in[4];
    const float* bd = (const float*)d_in[5];
    const float* Wo = (const float*)d_in[6];
    const float* bo = (const float*)d_in[7];
    float* out = (float*)d_out;

    k_init<<<416, 512>>>(x, A);
    for (int s = 0; s < 100; s++) {
        k_gemm1<<<dim3(32, 4), 256>>>();
        k_step<<<207, 512>>>(s, Wt, bt, Wd, bd);
    }
    k_out<<<dim3(32, 207), 256>>>(Wo, bo, out);
}

// round 4
// speedup vs baseline: 1.0009x; 1.0009x over previous
#include <cuda_runtime.h>
#include <cstdint>

#define NODES 207
#define HID   64
#define BATCH 64
#define BH    4096          // BATCH*HID
#define ROW   13248         // NODES*HID (per-batch state size)
#define HALF  423936u       // 32*ROW = offset between batch b and b+32 in flat index
#define KPAD  208           // 207 padded to multiple of 16
#define MPAD  256           // 207 padded to multiple of 64

// Scratch state (device globals: allocation-free rule)
__device__ float g_y[KPAD * BH];        // Y in [n][b*64+h] layout, row 207 = zeros
__device__ float g_AY[MPAD * BH];       // A @ Y
__device__ float g_Apad[MPAD * KPAD];   // zero-padded adjacency
__device__ unsigned int g_flat[256];    // per-step keys: (g_flat[2s], g_flat[2s+1])

// ---------------- JAX threefry2x32 (20 rounds) ----------------
__device__ __forceinline__ void tf2x32(unsigned k0, unsigned k1,
                                       unsigned x0, unsigned x1,
                                       unsigned &o0, unsigned &o1) {
    unsigned ks2 = k0 ^ k1 ^ 0x1BD11BDAu;
    x0 += k0; x1 += k1;
#define TFR(r) { x0 += x1; x1 = __funnelshift_l(x1, x1, (r)); x1 ^= x0; }
    TFR(13) TFR(15) TFR(26) TFR(6)
    x0 += k1;  x1 += ks2 + 1u;
    TFR(17) TFR(29) TFR(16) TFR(24)
    x0 += ks2; x1 += k0 + 2u;
    TFR(13) TFR(15) TFR(26) TFR(6)
    x0 += k0;  x1 += k1 + 3u;
    TFR(17) TFR(29) TFR(16) TFR(24)
    x0 += k1;  x1 += ks2 + 4u;
    TFR(13) TFR(15) TFR(26) TFR(6)
    x0 += ks2; x1 += k0 + 5u;
#undef TFR
    o0 = x0; o1 = x1;
}

// partitionable threefry: 32-bit word for counter i is xor of both outputs
__device__ __forceinline__ unsigned tf_bits32(unsigned k0, unsigned k1, unsigned i) {
    unsigned o0, o1;
    tf2x32(k0, k1, 0u, i, o0, o1);
    return o0 ^ o1;
}

// bits -> N(0,1) exactly as jax.random.normal (float32 path)
__device__ __forceinline__ float bits_to_normal(unsigned b) {
    float f = __uint_as_float((b >> 9) | 0x3F800000u) - 1.0f;  // [0,1)
    float u = fmaf(f, 2.0f, -0.99999994f);   // span(f32)=2.0, lo=nextafter(-1,0)
    u = fmaxf(u, -0.99999994f);
    return 1.41421356f * erfinvf(u);
}

// ---------------- init: transpose x -> g_y, pad A, compute step keys ----------------
__global__ void __launch_bounds__(512) k_init(const float* __restrict__ x,
                                              const float* __restrict__ A) {
    int gid = blockIdx.x * blockDim.x + threadIdx.x;
    int stride = gridDim.x * blockDim.x;
    for (int idx = gid; idx < KPAD * BH; idx += stride) {
        int n = idx >> 12, c = idx & 4095;
        float v = 0.0f;
        if (n < NODES) {
            int b = c >> 6, h = c & 63;
            v = x[b * ROW + n * HID + h];
        }
        g_y[idx] = v;
    }
    for (int idx = gid; idx < MPAD * KPAD; idx += stride) {
        int m = idx / KPAD, k = idx - m * KPAD;
        g_Apad[idx] = (m < NODES && k < NODES) ? A[m * NODES + k] : 0.0f;
    }
    // fold-like split (partitionable): key_s = threefry(key, 0, s), both words
    if (gid < 100) {
        unsigned o0, o1;
        tf2x32(0u, 42u, 0u, (unsigned)gid, o0, o1);
        g_flat[2 * gid]     = o0;
        g_flat[2 * gid + 1] = o1;
    }
}

// ---------------- GEMM1: g_AY[256,4096] = g_Apad[256,208] @ g_y[208,4096] ----------------
__global__ void __launch_bounds__(256) k_gemm1() {
    __shared__ float sA[16][64];    // k-major A tile
    __shared__ float sB[16][128];
    int n0 = blockIdx.x << 7;       // 32 col tiles of 128
    int m0 = blockIdx.y << 6;       // 4 row tiles of 64
    int tid = threadIdx.x;
    int tm = tid >> 4, tn = tid & 15;
    float acc[4][8];
#pragma unroll
    for (int r = 0; r < 4; r++)
#pragma unroll
        for (int c = 0; c < 8; c++) acc[r][c] = 0.0f;

    int lm = tid >> 2, lk = (tid & 3) << 2;
    for (int k0 = 0; k0 < KPAD; k0 += 16) {
        float4 a4 = *(const float4*)&g_Apad[(m0 + lm) * KPAD + k0 + lk];
        sA[lk + 0][lm] = a4.x; sA[lk + 1][lm] = a4.y;
        sA[lk + 2][lm] = a4.z; sA[lk + 3][lm] = a4.w;
#pragma unroll
        for (int i = 0; i < 2; i++) {
            int idx = tid + (i << 8);
            int kk = idx >> 5, c4 = idx & 31;
            *(float4*)&sB[kk][c4 << 2] =
                *(const float4*)&g_y[(k0 + kk) * BH + n0 + (c4 << 2)];
        }
        __syncthreads();
#pragma unroll
        for (int k = 0; k < 16; k++) {
            float4 av = *(const float4*)&sA[k][tm << 2];
            float4 b0 = *(const float4*)&sB[k][tn << 3];
            float4 b1 = *(const float4*)&sB[k][(tn << 3) + 4];
            float a[4] = {av.x, av.y, av.z, av.w};
            float bb[8] = {b0.x, b0.y, b0.z, b0.w, b1.x, b1.y, b1.z, b1.w};
#pragma unroll
            for (int r = 0; r < 4; r++)
#pragma unroll
                for (int c = 0; c < 8; c++)
                    acc[r][c] = fmaf(a[r], bb[c], acc[r][c]);
        }
        __syncthreads();
    }
#pragma unroll
    for (int r = 0; r < 4; r++) {
        float* dst = &g_AY[(m0 + (tm << 2) + r) * BH + n0 + (tn << 3)];
        *(float4*)dst       = make_float4(acc[r][0], acc[r][1], acc[r][2], acc[r][3]);
        *(float4*)(dst + 4) = make_float4(acc[r][4], acc[r][5], acc[r][6], acc[r][7]);
    }
}

// ---------------- step: two GCN heads + tanh + threefry noise + Euler-Maruyama update ----------------
// block n handles node n for all 64 batches; thread covers batches b and b+32.
__global__ void __launch_bounds__(512) k_step(int s,
        const float* __restrict__ Wt, const float* __restrict__ bt,
        const float* __restrict__ Wd, const float* __restrict__ bd) {
    __shared__ float sAY[64 * 65];          // [b][k], stride 65 (bank-conflict-free)
    int n = blockIdx.x;
    int tid = threadIdx.x;
    const float* ayrow = g_AY + n * BH;
    for (int idx = tid; idx < BH; idx += 512)
        sAY[(idx >> 6) * 65 + (idx & 63)] = ayrow[idx];
    __syncthreads();

    unsigned key0 = g_flat[2 * s], key1 = g_flat[2 * s + 1];
    int hq  = tid & 15;          // column quad (h = hq*4 + j)
    int blo = tid >> 4;          // 0..31
    float accT0[4] = {0,0,0,0}, accD0[4] = {0,0,0,0};
    float accT1[4] = {0,0,0,0}, accD1[4] = {0,0,0,0};
    const float4* Wt4 = (const float4*)Wt;
    const float4* Wd4 = (const float4*)Wd;
    const float* aL = &sAY[blo * 65];
    const float* aH = &sAY[(blo + 32) * 65];
#pragma unroll 8
    for (int k = 0; k < 64; k++) {
        float4 wt = __ldg(&Wt4[(k << 4) + hq]);
        float4 wd = __ldg(&Wd4[(k << 4) + hq]);
        float wtv[4] = {wt.x, wt.y, wt.z, wt.w};
        float wdv[4] = {wd.x, wd.y, wd.z, wd.w};
        float al = aL[k], ah = aH[k];
#pragma unroll
        for (int j = 0; j < 4; j++) {
            accT0[j] = fmaf(al, wtv[j], accT0[j]);
            accD0[j] = fmaf(al, wdv[j], accD0[j]);
            accT1[j] = fmaf(ah, wtv[j], accT1[j]);
            accD1[j] = fmaf(ah, wdv[j], accD1[j]);
        }
    }
    float4 bt4 = __ldg(&((const float4*)bt)[hq]);
    float4 bd4 = __ldg(&((const float4*)bd)[hq]);
    float btv[4] = {bt4.x, bt4.y, bt4.z, bt4.w};
    float bdv[4] = {bd4.x, bd4.y, bd4.z, bd4.w};

    // partitionable threefry noise: value index i = b*ROW + n*HID + h,
    // one eval per value, bits = out0 ^ out1 of tf(key_s, 0, i)
    float gl[4], gh[4];
    int baseidx = n * HID + (hq << 2);
#pragma unroll
    for (int j = 0; j < 4; j++) {
        unsigned ilo = (unsigned)(blo * ROW + baseidx + j);
        gl[j] = bits_to_normal(tf_bits32(key0, key1, ilo));
        gh[j] = bits_to_normal(tf_bits32(key0, key1, ilo + HALF));
    }

    float* yrow = g_y + n * BH;
    float4* pl = (float4*)&yrow[(blo << 6) + (hq << 2)];
    float4* ph = (float4*)&yrow[((blo + 32) << 6) + (hq << 2)];
    float4 vl4 = *pl, vh4 = *ph;
    float vl[4] = {vl4.x, vl4.y, vl4.z, vl4.w};
    float vh[4] = {vh4.x, vh4.y, vh4.z, vh4.w};
#pragma unroll
    for (int j = 0; j < 4; j++) {
        // y += (0.1*tanh)*dt + (0.1*tanh)*(sqrt_dt*g) ; dt=0.01, sqrt_dt=0.1
        vl[j] += 0.001f * tanhf(accT0[j] + btv[j]) + 0.01f * tanhf(accD0[j] + bdv[j]) * gl[j];
        vh[j] += 0.001f * tanhf(accT1[j] + btv[j]) + 0.01f * tanhf(accD1[j] + bdv[j]) * gh[j];
    }
    *pl = make_float4(vl[0], vl[1], vl[2], vl[3]);
    *ph = make_float4(vh[0], vh[1], vh[2], vh[3]);
}

// ---------------- output head: out[b,n,:,:] = tanh(y[b,n,:] @ W_out + b_out) ----------------
__global__ void __launch_bounds__(256) k_out(const float* __restrict__ Wo,
                                             const float* __restrict__ bo,
                                             float* __restrict__ out) {
    __shared__ float sY[BH];          // g_y row n (all 64 batches)
    __shared__ float sW[64 * 128];    // W_out[:, c0:c0+128]
    int n  = blockIdx.y;
    int c0 = blockIdx.x << 7;
    int tid = threadIdx.x;
    const float4* yr4 = (const float4*)(g_y + n * BH);
    for (int i = tid; i < 1024; i += 256) ((float4*)sY)[i] = yr4[i];
    for (int i = tid; i < 2048; i += 256) {
        int k = i >> 5, c4 = i & 31;
        ((float4*)sW)[(k << 5) + c4] = __ldg((const float4*)&Wo[k * BH + c0 + (c4 << 2)]);
    }
    __syncthreads();

    int cq = tid & 31;     // 32 col-quads -> 128 cols
    int bg = tid >> 5;     // warp id: rows b = bg + 8r
    float acc[8][4];
#pragma unroll
    for (int r = 0; r < 8; r++)
#pragma unroll
        for (int j = 0; j < 4; j++) acc[r][j] = 0.0f;
#pragma unroll 8
    for (int k = 0; k < 64; k++) {
        float4 w = *(const float4*)&sW[(k << 7) + (cq << 2)];
        float wv[4] = {w.x, w.y, w.z, w.w};
#pragma unroll
        for (int r = 0; r < 8; r++) {
            float a = sY[((bg + (r << 3)) << 6) + k];
#pragma unroll
            for (int j = 0; j < 4; j++)
                acc[r][j] = fmaf(a, wv[j], acc[r][j]);
        }
    }
    float4 bo4 = __ldg(&((const float4*)bo)[(c0 >> 2) + cq]);
    float bov[4] = {bo4.x, bo4.y, bo4.z, bo4.w};
#pragma unroll
    for (int r = 0; r < 8; r++) {
        int b = bg + (r << 3);
        float4 o;
        o.x = tanhf(acc[r][0] + bov[0]);
        o.y = tanhf(acc[r][1] + bov[1]);
        o.z = tanhf(acc[r][2] + bov[2]);
        o.w = tanhf(acc[r][3] + bov[3]);
        *(float4*)&out[(b * NODES + n) * 4096 + c0 + (cq << 2)] = o;
    }
}

// ---------------- host ----------------
extern "C" void kernel_launch(void* const* d_in, const int* in_sizes, int n_in,
                              void* d_out, int out_size) {
    const float* x  = (const float*)d_in[0];
    const float* A  = (const float*)d_in[1];
    const float* Wt = (const float*)d_in[2];
    const float* bt = (const float*)d_in[3];
    const float* Wd = (const float*)d_in[4];
    const float* bd = (const float*)d_in[5];
    const float* Wo = (const float*)d_in[6];
    const float* bo = (const float*)d_in[7];
    float* out = (float*)d_out;

    k_init<<<416, 512>>>(x, A);
    for (int s = 0; s < 100; s++) {
        k_gemm1<<<dim3(32, 4), 256>>>();
        k_step<<<207, 512>>>(s, Wt, bt, Wd, bd);
    }
    k_out<<<dim3(32, 207), 256>>>(Wo, bo, out);
}

// round 10
// speedup vs baseline: 1.4101x; 1.4088x over previous
#include <cuda_runtime.h>
#include <cstdint>

#define NODES 207
#define HID   64
#define BATCH 64
#define BH    4096          // BATCH*HID
#define ROW   13248         // NODES*HID
#define KPAD  224           // node dim padded (7 chunks of 32)
#define MPAD  256

// ---------------- device state ----------------
__device__ float g_y[KPAD * BH];        // Y [node][bh], rows 207..223 zero
__device__ float g_AY[MPAD * BH];       // A@Y [node][bh]
__device__ float g_Apad[MPAD * KPAD];   // padded adjacency
__device__ unsigned g_flat[256];        // per-step keys

// ---------------- threefry (partitionable) ----------------
__device__ __forceinline__ void tf2x32(unsigned k0, unsigned k1,
                                       unsigned x0, unsigned x1,
                                       unsigned &o0, unsigned &o1) {
    unsigned ks2 = k0 ^ k1 ^ 0x1BD11BDAu;
    x0 += k0; x1 += k1;
#define TFR(r) { x0 += x1; x1 = __funnelshift_l(x1, x1, (r)); x1 ^= x0; }
    TFR(13) TFR(15) TFR(26) TFR(6)
    x0 += k1;  x1 += ks2 + 1u;
    TFR(17) TFR(29) TFR(16) TFR(24)
    x0 += ks2; x1 += k0 + 2u;
    TFR(13) TFR(15) TFR(26) TFR(6)
    x0 += k0;  x1 += k1 + 3u;
    TFR(17) TFR(29) TFR(16) TFR(24)
    x0 += k1;  x1 += ks2 + 4u;
    TFR(13) TFR(15) TFR(26) TFR(6)
    x0 += ks2; x1 += k0 + 5u;
#undef TFR
    o0 = x0; o1 = x1;
}
__device__ __forceinline__ unsigned tf_bits32(unsigned k0, unsigned k1, unsigned i) {
    unsigned o0, o1;
    tf2x32(k0, k1, 0u, i, o0, o1);
    return o0 ^ o1;
}
__device__ __forceinline__ float bits_to_normal(unsigned b) {
    float f = __uint_as_float((b >> 9) | 0x3F800000u) - 1.0f;
    float u = fmaf(f, 2.0f, -0.99999994f);
    u = fmaxf(u, -0.99999994f);
    return 1.41421356f * erfinvf(u);
}

// round fp32 -> tf32 bit pattern (kept in a float)
__device__ __forceinline__ float tf32r(float x) {
    uint32_t r;
    asm("cvt.rna.tf32.f32 %0, %1;" : "=r"(r) : "f"(x));
    return __uint_as_float(r);
}

// ---------------- init ----------------
__global__ void __launch_bounds__(512) k_init(const float* __restrict__ x,
                                              const float* __restrict__ A) {
    int gid = blockIdx.x * blockDim.x + threadIdx.x;
    int stride = gridDim.x * blockDim.x;
    for (int idx = gid; idx < KPAD * BH; idx += stride) {
        int n = idx >> 12, c = idx & 4095;
        float v = 0.0f;
        if (n < NODES) {
            int b = c >> 6, h = c & 63;
            v = x[b * ROW + n * HID + h];
        }
        g_y[idx] = v;
    }
    for (int idx = gid; idx < MPAD * KPAD; idx += stride) {
        int m = idx / KPAD, k = idx - m * KPAD;
        g_Apad[idx] = (m < NODES && k < NODES) ? A[m * NODES + k] : 0.0f;
    }
    if (gid < 100) {
        unsigned o0, o1;
        tf2x32(0u, 42u, 0u, (unsigned)gid, o0, o1);
        g_flat[2 * gid]     = o0;
        g_flat[2 * gid + 1] = o1;
    }
}

// ---------------- GEMM1 via warp-mma tf32 ----------------
// AY[m 256][n 4096] = Apad[m][k 224] @ Y[k][n]; block tile 128m x 64n, grid (64, 2)
__global__ void __launch_bounds__(256) k_gemm() {
    __shared__ float sA[128][33];     // pad 33: fragment col reads conflict-free
    __shared__ float sB[32][136];     // pad 136: (8*tg + g) distinct banks
    int tid  = threadIdx.x;
    int lane = tid & 31, wid = tid >> 5;
    int n0 = blockIdx.x << 6;
    int m0 = blockIdx.y << 7;
    int wm = (wid >> 1) << 5;         // warp m offset: 0,32,64,96
    int wn = (wid & 1) << 5;          // warp n offset: 0,32
    int g  = lane >> 2, tg = lane & 3;

    float acc[2][4][4];
#pragma unroll
    for (int mi = 0; mi < 2; mi++)
#pragma unroll
        for (int ni = 0; ni < 4; ni++)
#pragma unroll
            for (int q = 0; q < 4; q++) acc[mi][ni][q] = 0.0f;

    for (int c = 0; c < 7; c++) {
        int k0 = c << 5;
        // stage A chunk [128][32], converted to tf32
#pragma unroll
        for (int i = 0; i < 4; i++) {
            int j = tid + (i << 8);               // 1024 float4
            int r = j >> 3, c4 = (j & 7) << 2;
            float4 v = *(const float4*)&g_Apad[(m0 + r) * KPAD + k0 + c4];
            sA[r][c4 + 0] = tf32r(v.x); sA[r][c4 + 1] = tf32r(v.y);
            sA[r][c4 + 2] = tf32r(v.z); sA[r][c4 + 3] = tf32r(v.w);
        }
        // stage B chunk [32][64], converted to tf32
#pragma unroll
        for (int i = 0; i < 2; i++) {
            int j = tid + (i << 8);               // 512 float4
            int r = j >> 4, c4 = (j & 15) << 2;
            float4 v = *(const float4*)&g_y[(k0 + r) * BH + n0 + c4];
            sB[r][c4 + 0] = tf32r(v.x); sB[r][c4 + 1] = tf32r(v.y);
            sB[r][c4 + 2] = tf32r(v.z); sB[r][c4 + 3] = tf32r(v.w);
        }
        __syncthreads();
#pragma unroll
        for (int kk = 0; kk < 4; kk++) {
            int kb = kk << 3;
            uint32_t a[2][4], b[4][2];
#pragma unroll
            for (int mi = 0; mi < 2; mi++) {
                int r = wm + (mi << 4) + g;
                a[mi][0] = __float_as_uint(sA[r    ][kb + tg]);
                a[mi][1] = __float_as_uint(sA[r + 8][kb + tg]);
                a[mi][2] = __float_as_uint(sA[r    ][kb + tg + 4]);
                a[mi][3] = __float_as_uint(sA[r + 8][kb + tg + 4]);
            }
#pragma unroll
            for (int ni = 0; ni < 4; ni++) {
                int cn = wn + (ni << 3) + g;
                b[ni][0] = __float_as_uint(sB[kb + tg    ][cn]);
                b[ni][1] = __float_as_uint(sB[kb + tg + 4][cn]);
            }
#pragma unroll
            for (int mi = 0; mi < 2; mi++)
#pragma unroll
                for (int ni = 0; ni < 4; ni++)
                    asm volatile(
                        "mma.sync.aligned.m16n8k8.row.col.f32.tf32.tf32.f32 "
                        "{%0,%1,%2,%3}, {%4,%5,%6,%7}, {%8,%9}, {%0,%1,%2,%3};"
                        : "+f"(acc[mi][ni][0]), "+f"(acc[mi][ni][1]),
                          "+f"(acc[mi][ni][2]), "+f"(acc[mi][ni][3])
                        : "r"(a[mi][0]), "r"(a[mi][1]), "r"(a[mi][2]), "r"(a[mi][3]),
                          "r"(b[ni][0]), "r"(b[ni][1]));
        }
        __syncthreads();
    }
#pragma unroll
    for (int mi = 0; mi < 2; mi++)
#pragma unroll
        for (int ni = 0; ni < 4; ni++) {
            int row = m0 + wm + (mi << 4) + g;
            int col = n0 + wn + (ni << 3) + (tg << 1);
            *(float2*)&g_AY[row * BH + col]       = make_float2(acc[mi][ni][0], acc[mi][ni][1]);
            *(float2*)&g_AY[(row + 8) * BH + col] = make_float2(acc[mi][ni][2], acc[mi][ni][3]);
        }
}

// ---------------- step: GCN heads + tanh + threefry + EM update ----------------
// grid (207 nodes, 2 batch-halves) x 256 threads; weights staged in smem
__global__ void __launch_bounds__(256) k_step(int s,
        const float* __restrict__ Wt, const float* __restrict__ bt,
        const float* __restrict__ Wd, const float* __restrict__ bd) {
    __shared__ float sAY[32 * 65];
    __shared__ float sWt[64 * 64];
    __shared__ float sWd[64 * 64];
    int n = blockIdx.x;
    int bhalf = blockIdx.y;
    int bh0 = bhalf << 11;
    int tid = threadIdx.x;
    const float* ayrow = g_AY + n * BH + bh0;
    for (int idx = tid; idx < 2048; idx += 256)
        sAY[(idx >> 6) * 65 + (idx & 63)] = ayrow[idx];
    for (int i = tid; i < 1024; i += 256) {
        ((float4*)sWt)[i] = __ldg(&((const float4*)Wt)[i]);
        ((float4*)sWd)[i] = __ldg(&((const float4*)Wd)[i]);
    }
    __syncthreads();

    unsigned key0 = g_flat[2 * s], key1 = g_flat[2 * s + 1];
    int hq = tid & 15;
    int bl = tid >> 4;
    float accT0[4] = {0,0,0,0}, accD0[4] = {0,0,0,0};
    float accT1[4] = {0,0,0,0}, accD1[4] = {0,0,0,0};
    const float* aL = &sAY[bl * 65];
    const float* aH = &sAY[(bl + 16) * 65];
#pragma unroll 8
    for (int k = 0; k < 64; k++) {
        float4 wt = *(const float4*)&sWt[(k << 6) + (hq << 2)];
        float4 wd = *(const float4*)&sWd[(k << 6) + (hq << 2)];
        float wtv[4] = {wt.x, wt.y, wt.z, wt.w};
        float wdv[4] = {wd.x, wd.y, wd.z, wd.w};
        float al = aL[k], ah = aH[k];
#pragma unroll
        for (int j = 0; j < 4; j++) {
            accT0[j] = fmaf(al, wtv[j], accT0[j]);
            accD0[j] = fmaf(al, wdv[j], accD0[j]);
            accT1[j] = fmaf(ah, wtv[j], accT1[j]);
            accD1[j] = fmaf(ah, wdv[j], accD1[j]);
        }
    }
    float4 bt4 = __ldg(&((const float4*)bt)[hq]);
    float4 bd4 = __ldg(&((const float4*)bd)[hq]);
    float btv[4] = {bt4.x, bt4.y, bt4.z, bt4.w};
    float bdv[4] = {bd4.x, bd4.y, bd4.z, bd4.w};

    int bA = bhalf * 32 + bl;
    int bB = bA + 16;
    float gl[4], gh[4];
    int baseidx = n * HID + (hq << 2);
#pragma unroll
    for (int j = 0; j < 4; j++) {
        gl[j] = bits_to_normal(tf_bits32(key0, key1, (unsigned)(bA * ROW + baseidx + j)));
        gh[j] = bits_to_normal(tf_bits32(key0, key1, (unsigned)(bB * ROW + baseidx + j)));
    }

    float* yrow = g_y + n * BH;
    float4* pl = (float4*)&yrow[(bA << 6) + (hq << 2)];
    float4* ph = (float4*)&yrow[(bB << 6) + (hq << 2)];
    float4 vl4 = *pl, vh4 = *ph;
    float vl[4] = {vl4.x, vl4.y, vl4.z, vl4.w};
    float vh[4] = {vh4.x, vh4.y, vh4.z, vh4.w};
#pragma unroll
    for (int j = 0; j < 4; j++) {
        vl[j] += 0.001f * tanhf(accT0[j] + btv[j]) + 0.01f * tanhf(accD0[j] + bdv[j]) * gl[j];
        vh[j] += 0.001f * tanhf(accT1[j] + btv[j]) + 0.01f * tanhf(accD1[j] + bdv[j]) * gh[j];
    }
    *pl = make_float4(vl[0], vl[1], vl[2], vl[3]);
    *ph = make_float4(vh[0], vh[1], vh[2], vh[3]);
}

// ---------------- output head (exact fp32) ----------------
__global__ void __launch_bounds__(256) k_out(const float* __restrict__ Wo,
                                             const float* __restrict__ bo,
                                             float* __restrict__ out) {
    __shared__ float sY[BH];
    __shared__ float sW[64 * 128];
    int n  = blockIdx.y;
    int c0 = blockIdx.x << 7;
    int tid = threadIdx.x;
    const float4* yr4 = (const float4*)(g_y + n * BH);
    for (int i = tid; i < 1024; i += 256) ((float4*)sY)[i] = yr4[i];
    for (int i = tid; i < 2048; i += 256) {
        int k = i >> 5, c4 = i & 31;
        ((float4*)sW)[(k << 5) + c4] = __ldg((const float4*)&Wo[k * BH + c0 + (c4 << 2)]);
    }
    __syncthreads();

    int cq = tid & 31;
    int bg = tid >> 5;
    float acc[8][4];
#pragma unroll
    for (int r = 0; r < 8; r++)
#pragma unroll
        for (int j = 0; j < 4; j++) acc[r][j] = 0.0f;
#pragma unroll 8
    for (int k = 0; k < 64; k++) {
        float4 w = *(const float4*)&sW[(k << 7) + (cq << 2)];
        float wv[4] = {w.x, w.y, w.z, w.w};
#pragma unroll
        for (int r = 0; r < 8; r++) {
            float a = sY[((bg + (r << 3)) << 6) + k];
#pragma unroll
            for (int j = 0; j < 4; j++)
                acc[r][j] = fmaf(a, wv[j], acc[r][j]);
        }
    }
    float4 bo4 = __ldg(&((const float4*)bo)[(c0 >> 2) + cq]);
    float bov[4] = {bo4.x, bo4.y, bo4.z, bo4.w};
#pragma unroll
    for (int r = 0; r < 8; r++) {
        int b = bg + (r << 3);
        float4 o;
        o.x = tanhf(acc[r][0] + bov[0]);
        o.y = tanhf(acc[r][1] + bov[1]);
        o.z = tanhf(acc[r][2] + bov[2]);
        o.w = tanhf(acc[r][3] + bov[3]);
        *(float4*)&out[(b * NODES + n) * 4096 + c0 + (cq << 2)] = o;
    }
}

// ---------------- host ----------------
extern "C" void kernel_launch(void* const* d_in, const int* in_sizes, int n_in,
                              void* d_out, int out_size) {
    const float* x  = (const float*)d_in[0];
    const float* A  = (const float*)d_in[1];
    const float* Wt = (const float*)d_in[2];
    const float* bt = (const float*)d_in[3];
    const float* Wd = (const float*)d_in[4];
    const float* bd = (const float*)d_in[5];
    const float* Wo = (const float*)d_in[6];
    const float* bo = (const float*)d_in[7];
    float* out = (float*)d_out;

    k_init<<<416, 512>>>(x, A);
    for (int s = 0; s < 100; s++) {
        k_gemm<<<dim3(64, 2), 256>>>();
        k_step<<<dim3(207, 2), 256>>>(s, Wt, bt, Wd, bd);
    }
    k_out<<<dim3(32, 207), 256>>>(Wo, bo, out);
}

// round 11
// speedup vs baseline: 2.7283x; 1.9349x over previous
#include <cuda_runtime.h>
#include <cstdint>

#define NODES 207
#define HID   64
#define BATCH 64
#define BH    4096          // BATCH*HID
#define ROW   13248         // NODES*HID
#define KPAD  224           // node dim padded (7 chunks of 32)
#define MPAD  256

// ---------------- device state ----------------
__device__ float g_yA[KPAD * BH];       // y ping  [node][bh], rows 207..223 zero
__device__ float g_yB[KPAD * BH];       // y pong
__device__ float g_ApadT[KPAD * MPAD];  // A^T: [k][m], constant
__device__ unsigned g_flat[256];        // per-step keys

// ---------------- threefry (partitionable) ----------------
__device__ __forceinline__ void tf2x32(unsigned k0, unsigned k1,
                                       unsigned x0, unsigned x1,
                                       unsigned &o0, unsigned &o1) {
    unsigned ks2 = k0 ^ k1 ^ 0x1BD11BDAu;
    x0 += k0; x1 += k1;
#define TFR(r) { x0 += x1; x1 = __funnelshift_l(x1, x1, (r)); x1 ^= x0; }
    TFR(13) TFR(15) TFR(26) TFR(6)
    x0 += k1;  x1 += ks2 + 1u;
    TFR(17) TFR(29) TFR(16) TFR(24)
    x0 += ks2; x1 += k0 + 2u;
    TFR(13) TFR(15) TFR(26) TFR(6)
    x0 += k0;  x1 += k1 + 3u;
    TFR(17) TFR(29) TFR(16) TFR(24)
    x0 += k1;  x1 += ks2 + 4u;
    TFR(13) TFR(15) TFR(26) TFR(6)
    x0 += ks2; x1 += k0 + 5u;
#undef TFR
    o0 = x0; o1 = x1;
}
__device__ __forceinline__ unsigned tf_bits32(unsigned k0, unsigned k1, unsigned i) {
    unsigned o0, o1;
    tf2x32(k0, k1, 0u, i, o0, o1);
    return o0 ^ o1;
}
__device__ __forceinline__ float bits_to_normal(unsigned b) {
    float f = __uint_as_float((b >> 9) | 0x3F800000u) - 1.0f;
    float u = fmaf(f, 2.0f, -0.99999994f);
    u = fmaxf(u, -0.99999994f);
    return 1.41421356f * erfinvf(u);
}

// ---------------- async-copy helpers ----------------
__device__ __forceinline__ uint32_t smem_u32(const void* p) {
    uint32_t a;
    asm("{ .reg .u64 t; cvta.to.shared.u64 t, %1; cvt.u32.u64 %0, t; }" : "=r"(a) : "l"(p));
    return a;
}
__device__ __forceinline__ void cpa16(uint32_t s, const void* g) {
    asm volatile("{ .reg .u64 ga; cvta.to.global.u64 ga, %1; "
                 "cp.async.cg.shared.global [%0], [ga], 16; }"
                 :: "r"(s), "l"(g));
}
#define CP_COMMIT() asm volatile("cp.async.commit_group;" ::: "memory")
#define CP_WAIT1()  asm volatile("cp.async.wait_group 1;" ::: "memory")
#define CP_WAIT0()  asm volatile("cp.async.wait_group 0;" ::: "memory")

#define MMA_TF32(acc, a, b) \
    asm volatile("mma.sync.aligned.m16n8k8.row.col.f32.tf32.tf32.f32 " \
        "{%0,%1,%2,%3}, {%4,%5,%6,%7}, {%8,%9}, {%0,%1,%2,%3};" \
        : "+f"((acc)[0]), "+f"((acc)[1]), "+f"((acc)[2]), "+f"((acc)[3]) \
        : "r"((a)[0]), "r"((a)[1]), "r"((a)[2]), "r"((a)[3]), \
          "r"((b)[0]), "r"((b)[1]))

// smem float offsets for k_fused
#define O_PA(p)  ((p) * 2304)             // A^T buf: [32][72]
#define O_PB(p)  (4608 + (p) * 2304)      // B buf:   [32][72]
#define O_AY     0                        // epilogue AY: [64][68] (reuses pipe bufs)
#define O_WT     9216                     // Wt: [64][72]
#define O_WD     13824                    // Wd: [64][72]
#define SMEM_FUSED ((13824 + 4608) * 4)   // 73728 bytes

// ---------------- init ----------------
__global__ void __launch_bounds__(512) k_init(const float* __restrict__ x,
                                              const float* __restrict__ A) {
    int gid = blockIdx.x * blockDim.x + threadIdx.x;
    int stride = gridDim.x * blockDim.x;
    for (int idx = gid; idx < KPAD * BH; idx += stride) {
        int n = idx >> 12, c = idx & 4095;
        float v = 0.0f;
        if (n < NODES) {
            int b = c >> 6, h = c & 63;
            v = x[b * ROW + n * HID + h];
        }
        g_yA[idx] = v;
        g_yB[idx] = 0.0f;
    }
    for (int idx = gid; idx < KPAD * MPAD; idx += stride) {
        int k = idx >> 8, m = idx & 255;
        g_ApadT[idx] = (m < NODES && k < NODES) ? A[m * NODES + k] : 0.0f;
    }
    if (gid < 100) {
        unsigned o0, o1;
        tf2x32(0u, 42u, 0u, (unsigned)gid, o0, o1);
        g_flat[2 * gid]     = o0;
        g_flat[2 * gid + 1] = o1;
    }
}

// ---------------- fused step: A@Y (tf32 mma, cp.async pipeline) + GCN heads + EM update ----------------
// grid (64 batches, 4 m-tiles) x 256 threads. n-tile 64 = one batch's h-range.
__global__ void __launch_bounds__(256) k_fused(int s,
        const float* __restrict__ Wt, const float* __restrict__ bt,
        const float* __restrict__ Wd, const float* __restrict__ bd) {
    extern __shared__ float sm[];
    const float* yR = (s & 1) ? g_yB : g_yA;
    float*       yW = (s & 1) ? g_yA : g_yB;
    int tid = threadIdx.x, lane = tid & 31, wid = tid >> 5;
    int bx = blockIdx.x;           // batch
    int n0 = bx << 6;              // bh column base
    int m0 = blockIdx.y << 6;      // node-row base
    int wm = (wid >> 2) << 5;      // warp m: 0,32
    int wn = (wid & 3) << 4;       // warp n: 0,16,32,48
    int g = lane >> 2, tg = lane & 3;
    uint32_t smb = smem_u32(sm);

#define STAGE_CHUNK(c, p) do { \
    _Pragma("unroll") \
    for (int i_ = 0; i_ < 2; i_++) { \
        int t_ = tid + (i_ << 8); \
        int r_ = t_ >> 4, c4_ = (t_ & 15) << 2; \
        cpa16(smb + (uint32_t)((O_PA(p) + r_ * 72 + c4_) << 2), \
              g_ApadT + ((c) * 32 + r_) * 256 + m0 + c4_); \
        cpa16(smb + (uint32_t)((O_PB(p) + r_ * 72 + c4_) << 2), \
              yR + ((c) * 32 + r_) * 4096 + n0 + c4_); \
    } \
} while (0)

    // prologue: W tiles + chunks 0,1
#pragma unroll
    for (int i = 0; i < 4; i++) {
        int t = tid + (i << 8);
        int r = t >> 4, c4 = (t & 15) << 2;
        cpa16(smb + (uint32_t)((O_WT + r * 72 + c4) << 2), Wt + r * 64 + c4);
        cpa16(smb + (uint32_t)((O_WD + r * 72 + c4) << 2), Wd + r * 64 + c4);
    }
    STAGE_CHUNK(0, 0);
    CP_COMMIT();
    STAGE_CHUNK(1, 1);
    CP_COMMIT();

    // noise for this thread's 16 output elements (overlaps cp.async latency)
    unsigned key0 = g_flat[2 * s], key1 = g_flat[2 * s + 1];
    float ns[2][2][4];
#pragma unroll
    for (int mi = 0; mi < 2; mi++)
#pragma unroll
        for (int ni = 0; ni < 2; ni++)
#pragma unroll
            for (int q = 0; q < 4; q++) {
                int node = m0 + wm + (mi << 4) + g + ((q >> 1) << 3);
                int h = wn + (ni << 3) + (tg << 1) + (q & 1);
                unsigned i = (unsigned)(bx * ROW + node * HID + h);
                ns[mi][ni][q] = bits_to_normal(tf_bits32(key0, key1, i));
            }

    // main loop: AY tile accumulation
    float acc[2][2][4];
#pragma unroll
    for (int mi = 0; mi < 2; mi++)
#pragma unroll
        for (int ni = 0; ni < 2; ni++)
#pragma unroll
            for (int q = 0; q < 4; q++) acc[mi][ni][q] = 0.0f;

    for (int c = 0; c < 7; c++) {
        int p = c & 1;
        if (c < 6) CP_WAIT1(); else CP_WAIT0();
        __syncthreads();
        const float* bufA = sm + O_PA(p);
        const float* bufB = sm + O_PB(p);
#pragma unroll
        for (int kk = 0; kk < 4; kk++) {
            int kb = kk << 3;
            uint32_t a[2][4], b[2][2];
#pragma unroll
            for (int mi = 0; mi < 2; mi++) {
                int rm = wm + (mi << 4) + g;
                a[mi][0] = __float_as_uint(bufA[(kb + tg) * 72 + rm]);
                a[mi][1] = __float_as_uint(bufA[(kb + tg) * 72 + rm + 8]);
                a[mi][2] = __float_as_uint(bufA[(kb + tg + 4) * 72 + rm]);
                a[mi][3] = __float_as_uint(bufA[(kb + tg + 4) * 72 + rm + 8]);
            }
#pragma unroll
            for (int ni = 0; ni < 2; ni++) {
                int cn = wn + (ni << 3) + g;
                b[ni][0] = __float_as_uint(bufB[(kb + tg) * 72 + cn]);
                b[ni][1] = __float_as_uint(bufB[(kb + tg + 4) * 72 + cn]);
            }
#pragma unroll
            for (int mi = 0; mi < 2; mi++)
#pragma unroll
                for (int ni = 0; ni < 2; ni++)
                    MMA_TF32(acc[mi][ni], a[mi], b[ni]);
        }
        __syncthreads();
        if (c + 2 <= 6) { STAGE_CHUNK(c + 2, p); CP_COMMIT(); }
    }

    // epilogue: AY tile -> smem [64][68]
#pragma unroll
    for (int mi = 0; mi < 2; mi++)
#pragma unroll
        for (int ni = 0; ni < 2; ni++) {
            int lr = wm + (mi << 4) + g;
            int cc = wn + (ni << 3) + (tg << 1);
            *(float2*)&sm[O_AY + lr * 68 + cc] = make_float2(acc[mi][ni][0], acc[mi][ni][1]);
            *(float2*)&sm[O_AY + (lr + 8) * 68 + cc] = make_float2(acc[mi][ni][2], acc[mi][ni][3]);
        }
    __syncthreads();

    // trend/diff heads: [64 node][64 h_in] @ W[64][64] via tf32 mma
    float aT[2][2][4], aD[2][2][4];
#pragma unroll
    for (int mi = 0; mi < 2; mi++)
#pragma unroll
        for (int ni = 0; ni < 2; ni++)
#pragma unroll
            for (int q = 0; q < 4; q++) { aT[mi][ni][q] = 0.0f; aD[mi][ni][q] = 0.0f; }

    const float* sWt = sm + O_WT;
    const float* sWd = sm + O_WD;
#pragma unroll
    for (int kk = 0; kk < 8; kk++) {
        int kb = kk << 3;
        uint32_t a2[2][4], b2t[2][2], b2d[2][2];
#pragma unroll
        for (int mi = 0; mi < 2; mi++) {
            int rm = wm + (mi << 4) + g;
            a2[mi][0] = __float_as_uint(sm[O_AY + rm * 68 + kb + tg]);
            a2[mi][1] = __float_as_uint(sm[O_AY + (rm + 8) * 68 + kb + tg]);
            a2[mi][2] = __float_as_uint(sm[O_AY + rm * 68 + kb + tg + 4]);
            a2[mi][3] = __float_as_uint(sm[O_AY + (rm + 8) * 68 + kb + tg + 4]);
        }
#pragma unroll
        for (int ni = 0; ni < 2; ni++) {
            int cn = wn + (ni << 3) + g;
            b2t[ni][0] = __float_as_uint(sWt[(kb + tg) * 72 + cn]);
            b2t[ni][1] = __float_as_uint(sWt[(kb + tg + 4) * 72 + cn]);
            b2d[ni][0] = __float_as_uint(sWd[(kb + tg) * 72 + cn]);
            b2d[ni][1] = __float_as_uint(sWd[(kb + tg + 4) * 72 + cn]);
        }
#pragma unroll
        for (int mi = 0; mi < 2; mi++)
#pragma unroll
            for (int ni = 0; ni < 2; ni++) {
                MMA_TF32(aT[mi][ni], a2[mi], b2t[ni]);
                MMA_TF32(aD[mi][ni], a2[mi], b2d[ni]);
            }
    }

    // Euler-Maruyama update: y_next = y_prev + 0.001*tanh(T+bt) + 0.01*tanh(D+bd)*noise
#pragma unroll
    for (int mi = 0; mi < 2; mi++)
#pragma unroll
        for (int ni = 0; ni < 2; ni++) {
            int lr = wm + (mi << 4) + g;
            int cc = wn + (ni << 3) + (tg << 1);
            float2 btv = *(const float2*)&bt[cc];
            float2 bdv = *(const float2*)&bd[cc];
            int node0 = m0 + lr;
            if (node0 < NODES) {
                float2 yp = *(const float2*)&yR[node0 * BH + n0 + cc];
                float t0 = tanhf(aT[mi][ni][0] + btv.x);
                float t1 = tanhf(aT[mi][ni][1] + btv.y);
                float d0 = tanhf(aD[mi][ni][0] + bdv.x);
                float d1 = tanhf(aD[mi][ni][1] + bdv.y);
                float2 o;
                o.x = yp.x + 0.001f * t0 + 0.01f * d0 * ns[mi][ni][0];
                o.y = yp.y + 0.001f * t1 + 0.01f * d1 * ns[mi][ni][1];
                *(float2*)&yW[node0 * BH + n0 + cc] = o;
            }
            int node1 = node0 + 8;
            if (node1 < NODES) {
                float2 yp = *(const float2*)&yR[node1 * BH + n0 + cc];
                float t0 = tanhf(aT[mi][ni][2] + btv.x);
                float t1 = tanhf(aT[mi][ni][3] + btv.y);
                float d0 = tanhf(aD[mi][ni][2] + bdv.x);
                float d1 = tanhf(aD[mi][ni][3] + bdv.y);
                float2 o;
                o.x = yp.x + 0.001f * t0 + 0.01f * d0 * ns[mi][ni][2];
                o.y = yp.y + 0.001f * t1 + 0.01f * d1 * ns[mi][ni][3];
                *(float2*)&yW[node1 * BH + n0 + cc] = o;
            }
        }
#undef STAGE_CHUNK
}

// ---------------- output head (exact fp32) ----------------
__global__ void __launch_bounds__(256) k_out(const float* __restrict__ Wo,
                                             const float* __restrict__ bo,
                                             float* __restrict__ out) {
    __shared__ float sY[BH];
    __shared__ float sW[64 * 128];
    int n  = blockIdx.y;
    int c0 = blockIdx.x << 7;
    int tid = threadIdx.x;
    const float4* yr4 = (const float4*)(g_yA + n * BH);
    for (int i = tid; i < 1024; i += 256) ((float4*)sY)[i] = yr4[i];
    for (int i = tid; i < 2048; i += 256) {
        int k = i >> 5, c4 = i & 31;
        ((float4*)sW)[(k << 5) + c4] = __ldg((const float4*)&Wo[k * BH + c0 + (c4 << 2)]);
    }
    __syncthreads();

    int cq = tid & 31;
    int bg = tid >> 5;
    float acc[8][4];
#pragma unroll
    for (int r = 0; r < 8; r++)
#pragma unroll
        for (int j = 0; j < 4; j++) acc[r][j] = 0.0f;
#pragma unroll 8
    for (int k = 0; k < 64; k++) {
        float4 w = *(const float4*)&sW[(k << 7) + (cq << 2)];
        float wv[4] = {w.x, w.y, w.z, w.w};
#pragma unroll
        for (int r = 0; r < 8; r++) {
            float a = sY[((bg + (r << 3)) << 6) + k];
#pragma unroll
            for (int j = 0; j < 4; j++)
                acc[r][j] = fmaf(a, wv[j], acc[r][j]);
        }
    }
    float4 bo4 = __ldg(&((const float4*)bo)[(c0 >> 2) + cq]);
    float bov[4] = {bo4.x, bo4.y, bo4.z, bo4.w};
#pragma unroll
    for (int r = 0; r < 8; r++) {
        int b = bg + (r << 3);
        float4 o;
        o.x = tanhf(acc[r][0] + bov[0]);
        o.y = tanhf(acc[r][1] + bov[1]);
        o.z = tanhf(acc[r][2] + bov[2]);
        o.w = tanhf(acc[r][3] + bov[3]);
        *(float4*)&out[(b * NODES + n) * 4096 + c0 + (cq << 2)] = o;
    }
}

// ---------------- host ----------------
extern "C" void kernel_launch(void* const* d_in, const int* in_sizes, int n_in,
                              void* d_out, int out_size) {
    const float* x  = (const float*)d_in[0];
    const float* A  = (const float*)d_in[1];
    const float* Wt = (const float*)d_in[2];
    const float* bt = (const float*)d_in[3];
    const float* Wd = (const float*)d_in[4];
    const float* bd = (const float*)d_in[5];
    const float* Wo = (const float*)d_in[6];
    const float* bo = (const float*)d_in[7];
    float* out = (float*)d_out;

    cudaFuncSetAttribute(k_fused, cudaFuncAttributeMaxDynamicSharedMemorySize, SMEM_FUSED);

    k_init<<<416, 512>>>(x, A);
    for (int s = 0; s < 100; s++)
        k_fused<<<dim3(64, 4), 256, SMEM_FUSED>>>(s, Wt, bt, Wd, bd);
    k_out<<<dim3(32, 207), 256>>>(Wo, bo, out);
}

// round 12
// speedup vs baseline: 2.8093x; 1.0297x over previous
#include <cuda_runtime.h>
#include <cstdint>

#define NODES 207
#define HID   64
#define BATCH 64
#define BH    4096          // BATCH*HID
#define ROW   13248         // NODES*HID
#define KPAD  224           // node dim padded (7 chunks of 32)
#define MPAD  256

// ---------------- device state ----------------
__device__ float g_yA[KPAD * BH];       // y ping  [node][bh], rows 207..223 zero
__device__ float g_yB[KPAD * BH];       // y pong
__device__ float g_ApadT[KPAD * MPAD];  // A^T: [k][m], constant
__device__ unsigned g_flat[256];        // per-step keys

// ---------------- threefry (partitionable) ----------------
__device__ __forceinline__ void tf2x32(unsigned k0, unsigned k1,
                                       unsigned x0, unsigned x1,
                                       unsigned &o0, unsigned &o1) {
    unsigned ks2 = k0 ^ k1 ^ 0x1BD11BDAu;
    x0 += k0; x1 += k1;
#define TFR(r) { x0 += x1; x1 = __funnelshift_l(x1, x1, (r)); x1 ^= x0; }
    TFR(13) TFR(15) TFR(26) TFR(6)
    x0 += k1;  x1 += ks2 + 1u;
    TFR(17) TFR(29) TFR(16) TFR(24)
    x0 += ks2; x1 += k0 + 2u;
    TFR(13) TFR(15) TFR(26) TFR(6)
    x0 += k0;  x1 += k1 + 3u;
    TFR(17) TFR(29) TFR(16) TFR(24)
    x0 += k1;  x1 += ks2 + 4u;
    TFR(13) TFR(15) TFR(26) TFR(6)
    x0 += ks2; x1 += k0 + 5u;
#undef TFR
    o0 = x0; o1 = x1;
}
__device__ __forceinline__ unsigned tf_bits32(unsigned k0, unsigned k1, unsigned i) {
    unsigned o0, o1;
    tf2x32(k0, k1, 0u, i, o0, o1);
    return o0 ^ o1;
}
__device__ __forceinline__ float bits_to_normal(unsigned b) {
    float f = __uint_as_float((b >> 9) | 0x3F800000u) - 1.0f;
    float u = fmaf(f, 2.0f, -0.99999994f);
    u = fmaxf(u, -0.99999994f);
    return 1.41421356f * erfinvf(u);
}

// ---------------- helpers ----------------
__device__ __forceinline__ uint32_t smem_u32(const void* p) {
    uint32_t a;
    asm("{ .reg .u64 t; cvta.to.shared.u64 t, %1; cvt.u32.u64 %0, t; }" : "=r"(a) : "l"(p));
    return a;
}
__device__ __forceinline__ void cpa16(uint32_t s, const void* g) {
    asm volatile("{ .reg .u64 ga; cvta.to.global.u64 ga, %1; "
                 "cp.async.cg.shared.global [%0], [ga], 16; }"
                 :: "r"(s), "l"(g));
}
#define CP_COMMIT() asm volatile("cp.async.commit_group;" ::: "memory")
#define CP_WAIT1()  asm volatile("cp.async.wait_group 1;" ::: "memory")
#define CP_WAIT0()  asm volatile("cp.async.wait_group 0;" ::: "memory")

__device__ __forceinline__ float tf32r(float x) {
    uint32_t r;
    asm("cvt.rna.tf32.f32 %0, %1;" : "=r"(r) : "f"(x));
    return __uint_as_float(r);
}

#define MMA_TF32(acc, a, b) \
    asm volatile("mma.sync.aligned.m16n8k8.row.col.f32.tf32.tf32.f32 " \
        "{%0,%1,%2,%3}, {%4,%5,%6,%7}, {%8,%9}, {%0,%1,%2,%3};" \
        : "+f"((acc)[0]), "+f"((acc)[1]), "+f"((acc)[2]), "+f"((acc)[3]) \
        : "r"((a)[0]), "r"((a)[1]), "r"((a)[2]), "r"((a)[3]), \
          "r"((b)[0]), "r"((b)[1]))

// k_fused smem layout (floats): pipes; AY overlays PA after main loop
#define O_PA(p)  ((p) * 1280)             // A^T chunk [32 k][32 m pad40]
#define O_PB(p)  (2560 + (p) * 2304)      // B chunk   [32 k][64 n pad72]
#define O_AY     0                        // AY tile   [32 m][64 k pad72] = 2304
#define SMF      7168                     // 28672 bytes

// ---------------- init ----------------
__global__ void __launch_bounds__(512) k_init(const float* __restrict__ x,
                                              const float* __restrict__ A) {
    int gid = blockIdx.x * blockDim.x + threadIdx.x;
    int stride = gridDim.x * blockDim.x;
    for (int idx = gid; idx < KPAD * BH; idx += stride) {
        int n = idx >> 12, c = idx & 4095;
        float v = 0.0f;
        if (n < NODES) {
            int b = c >> 6, h = c & 63;
            v = x[b * ROW + n * HID + h];
        }
        g_yA[idx] = v;
        g_yB[idx] = 0.0f;
    }
    for (int idx = gid; idx < KPAD * MPAD; idx += stride) {
        int k = idx >> 8, m = idx & 255;
        g_ApadT[idx] = (m < NODES && k < NODES) ? A[m * NODES + k] : 0.0f;
    }
    if (gid < 100) {
        unsigned o0, o1;
        tf2x32(0u, 42u, 0u, (unsigned)gid, o0, o1);
        g_flat[2 * gid]     = o0;
        g_flat[2 * gid + 1] = o1;
    }
}

// ---------------- fused step ----------------
// grid (64 batches, 7 m-tiles of 32) x 128 threads
__global__ void __launch_bounds__(128, 4) k_fused(int s,
        const float* __restrict__ Wt, const float* __restrict__ bt,
        const float* __restrict__ Wd, const float* __restrict__ bd) {
    __shared__ float sm[SMF];
    const float* yR = (s & 1) ? g_yB : g_yA;
    float*       yW = (s & 1) ? g_yA : g_yB;
    int tid = threadIdx.x, lane = tid & 31, wid = tid >> 5;
    int bx = blockIdx.x;           // batch
    int n0 = bx << 6;              // bh column base
    int m0 = blockIdx.y << 5;      // node-row base (0..192)
    int wm = (wid >> 1) << 4;      // warp m: 0,16
    int wn = (wid & 1) << 5;       // warp n: 0,32
    int g = lane >> 2, tg = lane & 3;
    uint32_t smb = smem_u32(sm);

#define STAGE_CHUNK(c, p) do { \
    _Pragma("unroll") \
    for (int i_ = 0; i_ < 2; i_++) { \
        int t_ = tid + (i_ << 7); \
        int r_ = t_ >> 3, cm_ = (t_ & 7) << 2; \
        cpa16(smb + (uint32_t)((O_PA(p) + r_ * 40 + cm_) << 2), \
              g_ApadT + ((c) * 32 + r_) * 256 + m0 + cm_); \
    } \
    _Pragma("unroll") \
    for (int i_ = 0; i_ < 4; i_++) { \
        int t_ = tid + (i_ << 7); \
        int r_ = t_ >> 4, cn_ = (t_ & 15) << 2; \
        cpa16(smb + (uint32_t)((O_PB(p) + r_ * 72 + cn_) << 2), \
              yR + ((c) * 32 + r_) * 4096 + n0 + cn_); \
    } \
} while (0)

    STAGE_CHUNK(0, 0);
    CP_COMMIT();
    STAGE_CHUNK(1, 1);
    CP_COMMIT();

    // noise (overlaps cp.async latency): element (node, h) of batch bx
    unsigned key0 = g_flat[2 * s], key1 = g_flat[2 * s + 1];
    float ns[4][4];
#pragma unroll
    for (int ni = 0; ni < 4; ni++)
#pragma unroll
        for (int q = 0; q < 4; q++) {
            int node = m0 + wm + g + ((q >> 1) << 3);
            int h = wn + (ni << 3) + (tg << 1) + (q & 1);
            ns[ni][q] = bits_to_normal(
                tf_bits32(key0, key1, (unsigned)(bx * ROW + node * HID + h)));
        }

    float acc[4][4];
#pragma unroll
    for (int ni = 0; ni < 4; ni++)
#pragma unroll
        for (int q = 0; q < 4; q++) acc[ni][q] = 0.0f;

    for (int c = 0; c < 7; c++) {
        int p = c & 1;
        if (c < 6) CP_WAIT1(); else CP_WAIT0();
        __syncthreads();
        const float* bufA = sm + O_PA(p);
        const float* bufB = sm + O_PB(p);
#pragma unroll
        for (int kk = 0; kk < 4; kk++) {
            int kb = kk << 3;
            uint32_t a[4], b[4][2];
            a[0] = __float_as_uint(bufA[(kb + tg) * 40 + wm + g]);
            a[1] = __float_as_uint(bufA[(kb + tg) * 40 + wm + g + 8]);
            a[2] = __float_as_uint(bufA[(kb + tg + 4) * 40 + wm + g]);
            a[3] = __float_as_uint(bufA[(kb + tg + 4) * 40 + wm + g + 8]);
#pragma unroll
            for (int ni = 0; ni < 4; ni++) {
                int cn = wn + (ni << 3) + g;
                b[ni][0] = __float_as_uint(bufB[(kb + tg) * 72 + cn]);
                b[ni][1] = __float_as_uint(bufB[(kb + tg + 4) * 72 + cn]);
            }
#pragma unroll
            for (int ni = 0; ni < 4; ni++)
                MMA_TF32(acc[ni], a, b[ni]);
        }
        __syncthreads();
        if (c + 2 <= 6) { STAGE_CHUNK(c + 2, p); CP_COMMIT(); }
    }

    // AY tile -> smem [32 m][64 k pad72] (overlays pipe-A buffers)
    __syncthreads();
#pragma unroll
    for (int ni = 0; ni < 4; ni++) {
        int lr = wm + g;
        int cc = wn + (ni << 3) + (tg << 1);
        *(float2*)&sm[O_AY + lr * 72 + cc] = make_float2(acc[ni][0], acc[ni][1]);
        *(float2*)&sm[O_AY + (lr + 8) * 72 + cc] = make_float2(acc[ni][2], acc[ni][3]);
    }
    __syncthreads();

    // trend/diff heads: AY[32 m][64 k] @ W[64 k][64 n], W frags via LDG (L1-hot)
    float aT[4][4], aD[4][4];
#pragma unroll
    for (int ni = 0; ni < 4; ni++)
#pragma unroll
        for (int q = 0; q < 4; q++) { aT[ni][q] = 0.0f; aD[ni][q] = 0.0f; }
#pragma unroll
    for (int kk = 0; kk < 8; kk++) {
        int kb = kk << 3;
        uint32_t a2[4];
        a2[0] = __float_as_uint(sm[O_AY + (wm + g) * 72 + kb + tg]);
        a2[1] = __float_as_uint(sm[O_AY + (wm + g + 8) * 72 + kb + tg]);
        a2[2] = __float_as_uint(sm[O_AY + (wm + g) * 72 + kb + tg + 4]);
        a2[3] = __float_as_uint(sm[O_AY + (wm + g + 8) * 72 + kb + tg + 4]);
#pragma unroll
        for (int ni = 0; ni < 4; ni++) {
            int cn = wn + (ni << 3) + g;
            uint32_t b2t[2], b2d[2];
            b2t[0] = __float_as_uint(__ldg(&Wt[(kb + tg) * 64 + cn]));
            b2t[1] = __float_as_uint(__ldg(&Wt[(kb + tg + 4) * 64 + cn]));
            b2d[0] = __float_as_uint(__ldg(&Wd[(kb + tg) * 64 + cn]));
            b2d[1] = __float_as_uint(__ldg(&Wd[(kb + tg + 4) * 64 + cn]));
            MMA_TF32(aT[ni], a2, b2t);
            MMA_TF32(aD[ni], a2, b2d);
        }
    }

    // Euler-Maruyama update
#pragma unroll
    for (int ni = 0; ni < 4; ni++) {
        int cc = wn + (ni << 3) + (tg << 1);
        float2 btv = __ldg((const float2*)&bt[cc]);
        float2 bdv = __ldg((const float2*)&bd[cc]);
        int node0 = m0 + wm + g;
        if (node0 < NODES) {
            float2 yp = *(const float2*)&yR[node0 * BH + n0 + cc];
            float2 o;
            o.x = yp.x + 0.001f * tanhf(aT[ni][0] + btv.x)
                       + 0.01f * tanhf(aD[ni][0] + bdv.x) * ns[ni][0];
            o.y = yp.y + 0.001f * tanhf(aT[ni][1] + btv.y)
                       + 0.01f * tanhf(aD[ni][1] + bdv.y) * ns[ni][1];
            *(float2*)&yW[node0 * BH + n0 + cc] = o;
        }
        int node1 = node0 + 8;
        if (node1 < NODES) {
            float2 yp = *(const float2*)&yR[node1 * BH + n0 + cc];
            float2 o;
            o.x = yp.x + 0.001f * tanhf(aT[ni][2] + btv.x)
                       + 0.01f * tanhf(aD[ni][2] + bdv.x) * ns[ni][2];
            o.y = yp.y + 0.001f * tanhf(aT[ni][3] + btv.y)
                       + 0.01f * tanhf(aD[ni][3] + bdv.y) * ns[ni][3];
            *(float2*)&yW[node1 * BH + n0 + cc] = o;
        }
    }
#undef STAGE_CHUNK
}

// ---------------- output head: 3xTF32 tensor MMA ----------------
// grid (16 col-tiles of 256, 207 nodes) x 256 threads
#define OY 0          // sY [64 b][64 k pad72] = 4608 floats
#define OW 4608       // sW [64 k][256 n pad260] = 16640 floats
#define SMO ((4608 + 16640) * 4)
__global__ void __launch_bounds__(256, 2) k_out(const float* __restrict__ Wo,
                                                const float* __restrict__ bo,
                                                float* __restrict__ out) {
    extern __shared__ float so[];
    int n  = blockIdx.y;
    int c0 = blockIdx.x << 8;
    int tid = threadIdx.x, lane = tid & 31, wid = tid >> 5;
    int wm = (wid >> 2) << 5;      // 0,32
    int wn = (wid & 3) << 6;       // 0,64,128,192
    int g = lane >> 2, tg = lane & 3;

#pragma unroll
    for (int i = 0; i < 4; i++) {
        int t = tid + (i << 8);
        int b = t >> 4, k4 = (t & 15) << 2;
        *(float4*)&so[OY + b * 72 + k4] = __ldg((const float4*)&g_yA[n * BH + b * 64 + k4]);
    }
#pragma unroll
    for (int i = 0; i < 16; i++) {
        int t = tid + (i << 8);
        int k = t >> 6, c4 = (t & 63) << 2;
        *(float4*)&so[OW + k * 260 + c4] = __ldg((const float4*)&Wo[k * BH + c0 + c4]);
    }
    __syncthreads();

    float acc[2][8][4];
#pragma unroll
    for (int mi = 0; mi < 2; mi++)
#pragma unroll
        for (int ni = 0; ni < 8; ni++)
#pragma unroll
            for (int q = 0; q < 4; q++) acc[mi][ni][q] = 0.0f;

#pragma unroll
    for (int kk = 0; kk < 8; kk++) {
        int kb = kk << 3;
        uint32_t ah[2][4], al[2][4];
#pragma unroll
        for (int mi = 0; mi < 2; mi++) {
            int rm = wm + (mi << 4) + g;
#pragma unroll
            for (int q = 0; q < 4; q++) {
                float v = so[OY + (rm + ((q & 1) << 3)) * 72 + kb + tg + ((q >> 1) << 2)];
                float h = tf32r(v);
                ah[mi][q] = __float_as_uint(h);
                al[mi][q] = __float_as_uint(tf32r(v - h));
            }
        }
#pragma unroll
        for (int ni = 0; ni < 8; ni++) {
            int cn = wn + (ni << 3) + g;
            float v0 = so[OW + (kb + tg) * 260 + cn];
            float v1 = so[OW + (kb + tg + 4) * 260 + cn];
            float h0 = tf32r(v0), h1 = tf32r(v1);
            uint32_t bh2[2] = {__float_as_uint(h0), __float_as_uint(h1)};
            uint32_t bl2[2] = {__float_as_uint(tf32r(v0 - h0)), __float_as_uint(tf32r(v1 - h1))};
#pragma unroll
            for (int mi = 0; mi < 2; mi++) {
                MMA_TF32(acc[mi][ni], ah[mi], bh2);
                MMA_TF32(acc[mi][ni], al[mi], bh2);
                MMA_TF32(acc[mi][ni], ah[mi], bl2);
            }
        }
    }

#pragma unroll
    for (int ni = 0; ni < 8; ni++) {
        int col = c0 + wn + (ni << 3) + (tg << 1);
        float2 bov = __ldg((const float2*)&bo[col]);
#pragma unroll
        for (int mi = 0; mi < 2; mi++) {
            int b0 = wm + (mi << 4) + g;
            float2 o0, o1;
            o0.x = tanhf(acc[mi][ni][0] + bov.x);
            o0.y = tanhf(acc[mi][ni][1] + bov.y);
            o1.x = tanhf(acc[mi][ni][2] + bov.x);
            o1.y = tanhf(acc[mi][ni][3] + bov.y);
            *(float2*)&out[(b0 * NODES + n) * 4096 + col] = o0;
            *(float2*)&out[((b0 + 8) * NODES + n) * 4096 + col] = o1;
        }
    }
}

// ---------------- host ----------------
extern "C" void kernel_launch(void* const* d_in, const int* in_sizes, int n_in,
                              void* d_out, int out_size) {
    const float* x  = (const float*)d_in[0];
    const float* A  = (const float*)d_in[1];
    const float* Wt = (const float*)d_in[2];
    const float* bt = (const float*)d_in[3];
    const float* Wd = (const float*)d_in[4];
    const float* bd = (const float*)d_in[5];
    const float* Wo = (const float*)d_in[6];
    const float* bo = (const float*)d_in[7];
    float* out = (float*)d_out;

    cudaFuncSetAttribute(k_out, cudaFuncAttributeMaxDynamicSharedMemorySize, SMO);

    k_init<<<416, 512>>>(x, A);
    for (int s = 0; s < 100; s++)
        k_fused<<<dim3(64, 7), 128>>>(s, Wt, bt, Wd, bd);
    k_out<<<dim3(16, 207), 256, SMO>>>(Wo, bo, out);
}